// round 3
// baseline (speedup 1.0000x reference)
#include <cuda_runtime.h>

// MinArchitecture scan: h_{t} = s*h_{t-1} + (1-s)*x_t
//   diff = h - x_t; u = d0*diff; t = tanh(u)
//   y' = c0 + c1*t + c2*t^2   (pre-halved so sigmoid(y) = 0.5 + 0.5*tanh(y'))
//   s = 0.5 + 0.5*tanh(y'); h = x_t + s*diff
// One thread per batch row, SEQ=512 steps.

#define SEQ 512
#define BLOCK 64

__device__ __forceinline__ float tanh_fast(float x) {
    float y;
    asm("tanh.approx.f32 %0, %1;" : "=f"(y) : "f"(x));
    return y;
}

#define STEP(XT) do {                                         \
    float diff = h - (XT);                                    \
    float tt   = tanh_fast(d0 * diff);                        \
    float yh   = fmaf(fmaf(c2, tt, c1), tt, c0);              \
    float s    = fmaf(0.5f, tanh_fast(yh), 0.5f);             \
    h          = fmaf(s, diff, (XT));                         \
} while (0)

#define STEP4(V) do { STEP((V).x); STEP((V).y); STEP((V).z); STEP((V).w); } while (0)

__global__ void __launch_bounds__(BLOCK) rnn_scan_kernel(
    const float* __restrict__ X,
    const float* __restrict__ W1,
    const float* __restrict__ W2,
    const float* __restrict__ bias,
    const float* __restrict__ Wz,
    const float* __restrict__ Ws,
    float* __restrict__ out)
{
    const int r = blockIdx.x * BLOCK + threadIdx.x;

    // ----- uniform scalar constants (broadcast loads, computed per-thread) -----
    // softmax over 2 elems: softmax(w)[0] = sigmoid(w0 - w1)
    const float a1 = 1.0f / (1.0f + expf(W1[1] - W1[0]));
    const float a2 = 1.0f / (1.0f + expf(W2[1] - W2[0]));
    const float d0 = a1 - a2;
    const float wz = Wz[0];
    const float ws = Ws[0];
    const float b  = bias[0];
    // y = b + ws*t + wz*(1 - 2 t^2); y' = y/2 = c0 + c1*t + c2*t^2
    const float c0 = 0.5f * (b + wz);
    const float c1 = 0.5f * ws;
    const float c2 = -wz;

    const float4* px = reinterpret_cast<const float4*>(X + (size_t)r * SEQ);

    // 16-float chunks (4 x float4), ping-pong double buffer.
    float4 A[4], B[4];

    #pragma unroll
    for (int j = 0; j < 4; ++j) A[j] = px[j];           // chunk 0
    #pragma unroll
    for (int j = 0; j < 4; ++j) B[j] = px[4 + j];       // chunk 1

    float h = A[0].x;   // h0 = X[:, 0]

    // chunk 0 (skip element 0 = h0)
    STEP(A[0].y); STEP(A[0].z); STEP(A[0].w);
    STEP4(A[1]); STEP4(A[2]); STEP4(A[3]);

    // chunks 1..31; B currently holds chunk 1
    #pragma unroll 1
    for (int c = 2; c < SEQ / 16; c += 2) {
        // prefetch chunk c into A (used later this iteration)
        #pragma unroll
        for (int j = 0; j < 4; ++j) A[j] = px[c * 4 + j];

        // process chunk c-1 (in B)
        STEP4(B[0]); STEP4(B[1]); STEP4(B[2]); STEP4(B[3]);

        // prefetch chunk c+1 into B (c max = 30 -> c+1 = 31, always in bounds)
        #pragma unroll
        for (int j = 0; j < 4; ++j) B[j] = px[(c + 1) * 4 + j];

        // process chunk c (in A)
        STEP4(A[0]); STEP4(A[1]); STEP4(A[2]); STEP4(A[3]);
    }

    // final chunk 31 (in B)
    STEP4(B[0]); STEP4(B[1]); STEP4(B[2]); STEP4(B[3]);

    out[r] = h;
}

extern "C" void kernel_launch(void* const* d_in, const int* in_sizes, int n_in,
                              void* d_out, int out_size)
{
    const float* X    = (const float*)d_in[0];
    const float* W1   = (const float*)d_in[1];
    const float* W2   = (const float*)d_in[2];
    const float* bias = (const float*)d_in[3];
    const float* Wz   = (const float*)d_in[4];
    const float* Ws   = (const float*)d_in[5];
    float* out = (float*)d_out;

    const int batch = out_size;                 // 65536
    const int grid  = (batch + BLOCK - 1) / BLOCK;
    rnn_scan_kernel<<<grid, BLOCK>>>(X, W1, W2, bias, Wz, Ws, out);
}